// round 2
// baseline (speedup 1.0000x reference)
#include <cuda_runtime.h>

// Problem-fixed shapes
#define B_    1
#define NCAM  6
#define DDIM  118
#define FH_   32
#define FW_   88
#define CC    80
#define NXV   360
#define NYV   360
#define NZV   1
#define NPTS  (NCAM * DDIM * FH_ * FW_)   // 1,993,728 frustum points

// Per-camera precomputed transforms (scratch: __device__ globals, no allocs)
__device__ float g_M[NCAM * 9];    // extra_rots @ c2l_rots @ inv(intrins)
__device__ float g_T[NCAM * 3];    // extra_rots @ c2l_trans + extra_trans
__device__ float g_iPR[NCAM * 9];  // inv(post_rots)
__device__ float g_pT[NCAM * 3];   // post_trans

__device__ __forceinline__ void inv3(const float* a, float* o) {
    float c00 = a[4] * a[8] - a[5] * a[7];
    float c01 = a[5] * a[6] - a[3] * a[8];
    float c02 = a[3] * a[7] - a[4] * a[6];
    float det = a[0] * c00 + a[1] * c01 + a[2] * c02;
    float id = 1.0f / det;
    o[0] = c00 * id;
    o[1] = (a[2] * a[7] - a[1] * a[8]) * id;
    o[2] = (a[1] * a[5] - a[2] * a[4]) * id;
    o[3] = c01 * id;
    o[4] = (a[0] * a[8] - a[2] * a[6]) * id;
    o[5] = (a[2] * a[3] - a[0] * a[5]) * id;
    o[6] = c02 * id;
    o[7] = (a[1] * a[6] - a[0] * a[7]) * id;
    o[8] = (a[0] * a[4] - a[1] * a[3]) * id;
}

__global__ void precompute_kernel(const float* __restrict__ c2l_r,
                                  const float* __restrict__ c2l_t,
                                  const float* __restrict__ intr,
                                  const float* __restrict__ post_r,
                                  const float* __restrict__ post_t,
                                  const float* __restrict__ extra_r,
                                  const float* __restrict__ extra_t) {
    int n = threadIdx.x;
    if (n >= NCAM) return;

    // inv(intrins)
    float iK[9];
    inv3(intr + n * 9, iK);

    // comb = c2l_rots[n] @ iK
    const float* R = c2l_r + n * 9;
    float comb[9];
#pragma unroll
    for (int i = 0; i < 3; i++)
#pragma unroll
        for (int j = 0; j < 3; j++)
            comb[i * 3 + j] = R[i * 3 + 0] * iK[0 * 3 + j] +
                              R[i * 3 + 1] * iK[1 * 3 + j] +
                              R[i * 3 + 2] * iK[2 * 3 + j];

    // M = extra_rots @ comb  (batch 0)
    const float* E = extra_r;
#pragma unroll
    for (int i = 0; i < 3; i++)
#pragma unroll
        for (int j = 0; j < 3; j++)
            g_M[n * 9 + i * 3 + j] = E[i * 3 + 0] * comb[0 * 3 + j] +
                                     E[i * 3 + 1] * comb[1 * 3 + j] +
                                     E[i * 3 + 2] * comb[2 * 3 + j];

    // T = extra_rots @ c2l_trans[n] + extra_trans
    const float* t = c2l_t + n * 3;
#pragma unroll
    for (int i = 0; i < 3; i++)
        g_T[n * 3 + i] = E[i * 3 + 0] * t[0] + E[i * 3 + 1] * t[1] +
                         E[i * 3 + 2] * t[2] + extra_t[i];

    // inv(post_rots)
    float iPR[9];
    inv3(post_r + n * 9, iPR);
#pragma unroll
    for (int i = 0; i < 9; i++) g_iPR[n * 9 + i] = iPR[i];
#pragma unroll
    for (int i = 0; i < 3; i++) g_pT[n * 3 + i] = post_t[n * 3 + i];
}

// One warp per frustum point. Warp-uniform geometry, then coalesced feature
// read + 80 channel atomics (RED.F32, destinations L2-resident).
__global__ __launch_bounds__(256) void scatter_kernel(const float* __restrict__ x,
                                                      float* __restrict__ out) {
    int warp = (int)((blockIdx.x * (unsigned)blockDim.x + threadIdx.x) >> 5);
    int lane = threadIdx.x & 31;
    if (warp >= NPTS) return;

    // decompose point -> (n, d, h, w)
    int w = warp % FW_;
    int t = warp / FW_;
    int h = t % FH_;
    t /= FH_;
    int d = t % DDIM;
    int n = t / DDIM;

    // frustum point [u, v, depth]
    float u = (float)w * (703.0f / 87.0f);  // linspace(0, 703, 88)
    float v = (float)h * (255.0f / 31.0f);  // linspace(0, 255, 32)
    float dep = 1.0f + 0.5f * (float)d;     // arange(1, 60, 0.5)

    const float* iPR = g_iPR + n * 9;
    const float* pT = g_pT + n * 3;
    const float* M = g_M + n * 9;
    const float* T = g_T + n * 3;

    // undo post-augmentation
    float ax = u - pT[0], ay = v - pT[1], az = dep - pT[2];
    float px = iPR[0] * ax + iPR[1] * ay + iPR[2] * az;
    float py = iPR[3] * ax + iPR[4] * ay + iPR[5] * az;
    float pz = iPR[6] * ax + iPR[7] * ay + iPR[8] * az;

    // undo perspective: (u*d, v*d, d)
    float rx = px * pz, ry = py * pz, rz = pz;

    // to lidar/ego frame
    float gx = M[0] * rx + M[1] * ry + M[2] * rz + T[0];
    float gy = M[3] * rx + M[4] * ry + M[5] * rz + T[1];
    float gz = M[6] * rx + M[7] * ry + M[8] * rz + T[2];

    // voxelize: (geom - (BX - DX/2)) / DX, int32 cast truncates toward zero
    // (exactly matches jnp astype(int32) semantics, incl. negative values)
    const float bx0 = -53.85f - 0.15f;  // -54.0
    const float by0 = -53.85f - 0.15f;
    const float bz0 = 0.0f - 10.0f;     // -10.0
    int cx = (int)((gx - bx0) / 0.3f);
    int cy = (int)((gy - by0) / 0.3f);
    int cz = (int)((gz - bz0) / 20.0f);

    if (cx < 0 || cx >= NXV || cy < 0 || cy >= NYV || cz < 0 || cz >= NZV)
        return;  // warp-uniform: skip feature read entirely

    int flat = (cz * NXV + cx) * NYV + cy;
    const float* f = x + (size_t)warp * CC;

#pragma unroll
    for (int c = lane; c < CC; c += 32) {
        atomicAdd(out + (size_t)c * (NZV * NXV * NYV) + flat, __ldg(f + c));
    }
}

extern "C" void kernel_launch(void* const* d_in, const int* in_sizes, int n_in,
                              void* d_out, int out_size) {
    const float* x       = (const float*)d_in[0];
    const float* c2l_r   = (const float*)d_in[1];
    const float* c2l_t   = (const float*)d_in[2];
    const float* intr    = (const float*)d_in[3];
    const float* post_r  = (const float*)d_in[4];
    const float* post_t  = (const float*)d_in[5];
    const float* extra_r = (const float*)d_in[6];
    const float* extra_t = (const float*)d_in[7];
    float* out = (float*)d_out;

    cudaMemsetAsync(out, 0, (size_t)out_size * sizeof(float));
    precompute_kernel<<<1, 32>>>(c2l_r, c2l_t, intr, post_r, post_t, extra_r, extra_t);

    // NPTS warps, 8 warps/block
    int blocks = NPTS / 8;  // 1,993,728 / 8 = 249,216
    scatter_kernel<<<blocks, 256>>>(x, out);
}

// round 3
// speedup vs baseline: 3.6089x; 3.6089x over previous
#include <cuda_runtime.h>

// Problem-fixed shapes
#define NCAM  6
#define DDIM  118
#define FH_   32
#define FW_   88
#define CC    80
#define NXV   360
#define NYV   360
#define NZV   1
#define NPOS  (NXV * NYV)                 // 129600 BEV positions
#define NPTS  (NCAM * DDIM * FH_ * FW_)   // 1,993,728 frustum points

// Per-camera precomputed transforms
__device__ float g_M[NCAM * 9];    // extra_rots @ c2l_rots @ inv(intrins)
__device__ float g_T[NCAM * 3];    // extra_rots @ c2l_trans + extra_trans
__device__ float g_iPR[NCAM * 9];  // inv(post_rots)
__device__ float g_pT[NCAM * 3];   // post_trans

// Channel-minor accumulation scratch: scratch[pos*CC + c].
// Zero at module load; finalize_kernel zero-restores it每 call => graph-replay safe.
__device__ float g_scratch[NPOS * CC];   // 41.47 MB, L2-resident

__device__ __forceinline__ void inv3(const float* a, float* o) {
    float c00 = a[4] * a[8] - a[5] * a[7];
    float c01 = a[5] * a[6] - a[3] * a[8];
    float c02 = a[3] * a[7] - a[4] * a[6];
    float det = a[0] * c00 + a[1] * c01 + a[2] * c02;
    float id = 1.0f / det;
    o[0] = c00 * id;
    o[1] = (a[2] * a[7] - a[1] * a[8]) * id;
    o[2] = (a[1] * a[5] - a[2] * a[4]) * id;
    o[3] = c01 * id;
    o[4] = (a[0] * a[8] - a[2] * a[6]) * id;
    o[5] = (a[2] * a[3] - a[0] * a[5]) * id;
    o[6] = c02 * id;
    o[7] = (a[1] * a[6] - a[0] * a[7]) * id;
    o[8] = (a[0] * a[4] - a[1] * a[3]) * id;
}

__global__ void precompute_kernel(const float* __restrict__ c2l_r,
                                  const float* __restrict__ c2l_t,
                                  const float* __restrict__ intr,
                                  const float* __restrict__ post_r,
                                  const float* __restrict__ post_t,
                                  const float* __restrict__ extra_r,
                                  const float* __restrict__ extra_t) {
    int n = threadIdx.x;
    if (n >= NCAM) return;

    float iK[9];
    inv3(intr + n * 9, iK);

    const float* R = c2l_r + n * 9;
    float comb[9];
#pragma unroll
    for (int i = 0; i < 3; i++)
#pragma unroll
        for (int j = 0; j < 3; j++)
            comb[i * 3 + j] = R[i * 3 + 0] * iK[0 * 3 + j] +
                              R[i * 3 + 1] * iK[1 * 3 + j] +
                              R[i * 3 + 2] * iK[2 * 3 + j];

    const float* E = extra_r;
#pragma unroll
    for (int i = 0; i < 3; i++)
#pragma unroll
        for (int j = 0; j < 3; j++)
            g_M[n * 9 + i * 3 + j] = E[i * 3 + 0] * comb[0 * 3 + j] +
                                     E[i * 3 + 1] * comb[1 * 3 + j] +
                                     E[i * 3 + 2] * comb[2 * 3 + j];

    const float* t = c2l_t + n * 3;
#pragma unroll
    for (int i = 0; i < 3; i++)
        g_T[n * 3 + i] = E[i * 3 + 0] * t[0] + E[i * 3 + 1] * t[1] +
                         E[i * 3 + 2] * t[2] + extra_t[i];

    float iPR[9];
    inv3(post_r + n * 9, iPR);
#pragma unroll
    for (int i = 0; i < 9; i++) g_iPR[n * 9 + i] = iPR[i];
#pragma unroll
    for (int i = 0; i < 3; i++) g_pT[n * 3 + i] = post_t[n * 3 + i];
}

// One warp per frustum point. Warp-uniform geometry; then lanes 0..19 each do
// one LDG.128 feature read + one red.global.add.v4.f32 into channel-minor scratch.
__global__ __launch_bounds__(256) void scatter_kernel(const float* __restrict__ x) {
    int warp = (int)((blockIdx.x * (unsigned)blockDim.x + threadIdx.x) >> 5);
    int lane = threadIdx.x & 31;
    if (warp >= NPTS) return;

    // decompose point -> (n, d, h, w)
    int w = warp % FW_;
    int t = warp / FW_;
    int h = t % FH_;
    t /= FH_;
    int d = t % DDIM;
    int n = t / DDIM;

    float u = (float)w * (703.0f / 87.0f);
    float v = (float)h * (255.0f / 31.0f);
    float dep = 1.0f + 0.5f * (float)d;

    const float* iPR = g_iPR + n * 9;
    const float* pT = g_pT + n * 3;
    const float* M = g_M + n * 9;
    const float* T = g_T + n * 3;

    float ax = u - pT[0], ay = v - pT[1], az = dep - pT[2];
    float px = iPR[0] * ax + iPR[1] * ay + iPR[2] * az;
    float py = iPR[3] * ax + iPR[4] * ay + iPR[5] * az;
    float pz = iPR[6] * ax + iPR[7] * ay + iPR[8] * az;

    float rx = px * pz, ry = py * pz, rz = pz;

    float gx = M[0] * rx + M[1] * ry + M[2] * rz + T[0];
    float gy = M[3] * rx + M[4] * ry + M[5] * rz + T[1];
    float gz = M[6] * rx + M[7] * ry + M[8] * rz + T[2];

    // voxelize: int32 cast truncates toward zero (matches jnp astype(int32))
    int cx = (int)((gx + 54.0f) * (1.0f / 0.3f));
    int cy = (int)((gy + 54.0f) * (1.0f / 0.3f));
    int cz = (int)((gz + 10.0f) * (1.0f / 20.0f));

    if (cx < 0 || cx >= NXV || cy < 0 || cy >= NYV || cz < 0 || cz >= NZV)
        return;

    int flat = cx * NYV + cy;

    if (lane < CC / 4) {  // lanes 0..19
        const float4* f = (const float4*)(x + (size_t)warp * CC) + lane;
        float4 val = __ldg(f);
        float* dst = g_scratch + (size_t)flat * CC + lane * 4;
        asm volatile("red.global.add.v4.f32 [%0], {%1, %2, %3, %4};"
                     :: "l"(dst), "f"(val.x), "f"(val.y), "f"(val.z), "f"(val.w)
                     : "memory");
    }
}

// Transpose scratch [pos, c] -> out [c, pos], and zero-restore scratch.
// Block handles 32 consecutive positions x 80 channels.
#define POS_TILE 32
__global__ __launch_bounds__(256) void finalize_kernel(float* __restrict__ out) {
    __shared__ float tile[CC * (POS_TILE + 1)];
    int pos0 = blockIdx.x * POS_TILE;
    int tid = threadIdx.x;

    float* src = g_scratch + (size_t)pos0 * CC;  // contiguous 2560 floats

    // load (coalesced) into smem as tile[c][p], then zero scratch region
#pragma unroll
    for (int i = 0; i < (POS_TILE * CC) / 256; i++) {
        int e = i * 256 + tid;
        int p = e / CC;
        int c = e % CC;
        tile[c * (POS_TILE + 1) + p] = src[e];
        src[e] = 0.0f;
    }
    __syncthreads();

    // write out (coalesced 128B segments per channel row)
#pragma unroll
    for (int i = 0; i < (POS_TILE * CC) / 256; i++) {
        int o = i * 256 + tid;
        int c = o / POS_TILE;
        int p = o % POS_TILE;
        out[(size_t)c * NPOS + pos0 + p] = tile[c * (POS_TILE + 1) + p];
    }
}

extern "C" void kernel_launch(void* const* d_in, const int* in_sizes, int n_in,
                              void* d_out, int out_size) {
    const float* x       = (const float*)d_in[0];
    const float* c2l_r   = (const float*)d_in[1];
    const float* c2l_t   = (const float*)d_in[2];
    const float* intr    = (const float*)d_in[3];
    const float* post_r  = (const float*)d_in[4];
    const float* post_t  = (const float*)d_in[5];
    const float* extra_r = (const float*)d_in[6];
    const float* extra_t = (const float*)d_in[7];
    float* out = (float*)d_out;

    precompute_kernel<<<1, 32>>>(c2l_r, c2l_t, intr, post_r, post_t, extra_r, extra_t);

    int blocks = NPTS / 8;  // 8 warps per 256-thread block
    scatter_kernel<<<blocks, 256>>>(x);

    finalize_kernel<<<NPOS / POS_TILE, 256>>>(out);  // 4050 blocks
}

// round 4
// speedup vs baseline: 8.2677x; 2.2909x over previous
#include <cuda_runtime.h>

// Problem-fixed shapes
#define NCAM  6
#define DDIM  118
#define FH_   32
#define FW_   88
#define CC    80
#define NXV   360
#define NYV   360
#define NZV   1
#define NPOS  (NXV * NYV)                  // 129600 BEV positions
#define NGRP  (NCAM * DDIM * FW_)          // 62304 (n,d,w) groups, 32 h's each

// Per-camera precomputed transforms
__device__ float g_M[NCAM * 9];    // extra_rots @ c2l_rots @ inv(intrins)
__device__ float g_T[NCAM * 3];    // extra_rots @ c2l_trans + extra_trans
__device__ float g_iPR[NCAM * 9];  // inv(post_rots)
__device__ float g_pT[NCAM * 3];   // post_trans

__device__ __forceinline__ void inv3(const float* a, float* o) {
    float c00 = a[4] * a[8] - a[5] * a[7];
    float c01 = a[5] * a[6] - a[3] * a[8];
    float c02 = a[3] * a[7] - a[4] * a[6];
    float det = a[0] * c00 + a[1] * c01 + a[2] * c02;
    float id = 1.0f / det;
    o[0] = c00 * id;
    o[1] = (a[2] * a[7] - a[1] * a[8]) * id;
    o[2] = (a[1] * a[5] - a[2] * a[4]) * id;
    o[3] = c01 * id;
    o[4] = (a[0] * a[8] - a[2] * a[6]) * id;
    o[5] = (a[2] * a[3] - a[0] * a[5]) * id;
    o[6] = c02 * id;
    o[7] = (a[1] * a[6] - a[0] * a[7]) * id;
    o[8] = (a[0] * a[4] - a[1] * a[3]) * id;
}

__global__ void precompute_kernel(const float* __restrict__ c2l_r,
                                  const float* __restrict__ c2l_t,
                                  const float* __restrict__ intr,
                                  const float* __restrict__ post_r,
                                  const float* __restrict__ post_t,
                                  const float* __restrict__ extra_r,
                                  const float* __restrict__ extra_t) {
    int n = threadIdx.x;
    if (n >= NCAM) return;

    float iK[9];
    inv3(intr + n * 9, iK);

    const float* R = c2l_r + n * 9;
    float comb[9];
#pragma unroll
    for (int i = 0; i < 3; i++)
#pragma unroll
        for (int j = 0; j < 3; j++)
            comb[i * 3 + j] = R[i * 3 + 0] * iK[0 * 3 + j] +
                              R[i * 3 + 1] * iK[1 * 3 + j] +
                              R[i * 3 + 2] * iK[2 * 3 + j];

    const float* E = extra_r;
#pragma unroll
    for (int i = 0; i < 3; i++)
#pragma unroll
        for (int j = 0; j < 3; j++)
            g_M[n * 9 + i * 3 + j] = E[i * 3 + 0] * comb[0 * 3 + j] +
                                     E[i * 3 + 1] * comb[1 * 3 + j] +
                                     E[i * 3 + 2] * comb[2 * 3 + j];

    const float* t = c2l_t + n * 3;
#pragma unroll
    for (int i = 0; i < 3; i++)
        g_T[n * 3 + i] = E[i * 3 + 0] * t[0] + E[i * 3 + 1] * t[1] +
                         E[i * 3 + 2] * t[2] + extra_t[i];

    float iPR[9];
    inv3(post_r + n * 9, iPR);
#pragma unroll
    for (int i = 0; i < 9; i++) g_iPR[n * 9 + i] = iPR[i];
#pragma unroll
    for (int i = 0; i < 3; i++) g_pT[n * 3 + i] = post_t[n * 3 + i];
}

// One warp per (n, d, w) group: lane l computes geometry for h = l. The warp
// then walks h = 0..31, register-accumulating the 80-ch feature vector while
// the BEV cell stays constant, flushing atomics only on cell change / end.
// For this problem's geometry h doesn't move (cx,cy), so atomic traffic drops
// ~32x vs per-point scatter. Feature reads for invalid h are skipped entirely.
__global__ __launch_bounds__(256) void scatter_kernel(const float* __restrict__ x,
                                                      float* __restrict__ out) {
    int grp = (int)((blockIdx.x * (unsigned)blockDim.x + threadIdx.x) >> 5);
    int lane = threadIdx.x & 31;
    if (grp >= NGRP) return;

    // group -> (n, d, w); consecutive groups = consecutive w (x-read locality)
    int w = grp % FW_;
    int nd = grp / FW_;      // n*DDIM + d
    int d = nd % DDIM;
    int n = nd / DDIM;
    int h = lane;            // each lane owns one image row

    float u = (float)w * (703.0f / 87.0f);
    float v = (float)h * (255.0f / 31.0f);
    float dep = 1.0f + 0.5f * (float)d;

    const float* iPR = g_iPR + n * 9;
    const float* pT = g_pT + n * 3;
    const float* M = g_M + n * 9;
    const float* T = g_T + n * 3;

    float ax = u - pT[0], ay = v - pT[1], az = dep - pT[2];
    float px = iPR[0] * ax + iPR[1] * ay + iPR[2] * az;
    float py = iPR[3] * ax + iPR[4] * ay + iPR[5] * az;
    float pz = iPR[6] * ax + iPR[7] * ay + iPR[8] * az;

    float rx = px * pz, ry = py * pz, rz = pz;

    float gx = M[0] * rx + M[1] * ry + M[2] * rz + T[0];
    float gy = M[3] * rx + M[4] * ry + M[5] * rz + T[1];
    float gz = M[6] * rx + M[7] * ry + M[8] * rz + T[2];

    // voxelize: int32 cast truncates toward zero (matches jnp astype(int32))
    int cx = (int)((gx + 54.0f) * (1.0f / 0.3f));
    int cy = (int)((gy + 54.0f) * (1.0f / 0.3f));
    int cz = (int)((gz + 10.0f) * (1.0f / 20.0f));

    bool valid = (cx >= 0) & (cx < NXV) & (cy >= 0) & (cy < NYV) &
                 (cz >= 0) & (cz < NZV);
    int voxel = valid ? (cx * NYV + cy) : -1;

    if (__ballot_sync(0xffffffffu, valid) == 0u) return;  // whole group out

    // x base for (n, d, h=0, w): stride between h's is FW_*CC floats
    const float* base = x + ((size_t)nd * FH_ + 0) * (FW_ * CC) + (size_t)w * CC;
    bool active = lane < (CC / 4);  // lanes 0..19 carry 4 channels each

    float4 acc = make_float4(0.f, 0.f, 0.f, 0.f);
    int cur = -1;

#pragma unroll
    for (int hh = 0; hh < FH_; hh++) {
        int vx = __shfl_sync(0xffffffffu, voxel, hh);
        if (vx < 0) continue;                 // invalid row: skip read
        if (vx != cur) {                      // warp-uniform
            if (cur >= 0 && active) {
#pragma unroll
                for (int i = 0; i < 4; i++)
                    atomicAdd(out + (size_t)(lane * 4 + i) * NPOS + cur,
                              ((const float*)&acc)[i]);
            }
            cur = vx;
            acc = make_float4(0.f, 0.f, 0.f, 0.f);
        }
        if (active) {
            float4 f = __ldg((const float4*)(base + (size_t)hh * (FW_ * CC)) + lane);
            acc.x += f.x; acc.y += f.y; acc.z += f.z; acc.w += f.w;
        }
    }
    if (cur >= 0 && active) {
#pragma unroll
        for (int i = 0; i < 4; i++)
            atomicAdd(out + (size_t)(lane * 4 + i) * NPOS + cur,
                      ((const float*)&acc)[i]);
    }
}

extern "C" void kernel_launch(void* const* d_in, const int* in_sizes, int n_in,
                              void* d_out, int out_size) {
    const float* x       = (const float*)d_in[0];
    const float* c2l_r   = (const float*)d_in[1];
    const float* c2l_t   = (const float*)d_in[2];
    const float* intr    = (const float*)d_in[3];
    const float* post_r  = (const float*)d_in[4];
    const float* post_t  = (const float*)d_in[5];
    const float* extra_r = (const float*)d_in[6];
    const float* extra_t = (const float*)d_in[7];
    float* out = (float*)d_out;

    cudaMemsetAsync(out, 0, (size_t)out_size * sizeof(float));
    precompute_kernel<<<1, 32>>>(c2l_r, c2l_t, intr, post_r, post_t, extra_r, extra_t);

    // NGRP warps, 8 warps per 256-thread block: 62304/8 = 7788 blocks
    scatter_kernel<<<NGRP / 8, 256>>>(x, out);
}

// round 5
// speedup vs baseline: 10.7243x; 1.2971x over previous
#include <cuda_runtime.h>

// Problem-fixed shapes
#define NCAM  6
#define DDIM  118
#define FH_   32
#define FW_   88
#define CC    80
#define NXV   360
#define NYV   360
#define NZV   1
#define NPOS  (NXV * NYV)                  // 129600 BEV positions
#define NGRP  (NCAM * DDIM * FW_)          // 62304 (n,d,w) groups, 32 h's each
#define HSTRIDE (FW_ * CC)                 // 7040 floats between h rows

// Per-camera precomputed transforms
__device__ float g_M[NCAM * 9];    // extra_rots @ c2l_rots @ inv(intrins)
__device__ float g_T[NCAM * 3];    // extra_rots @ c2l_trans + extra_trans
__device__ float g_iPR[NCAM * 9];  // inv(post_rots)
__device__ float g_pT[NCAM * 3];   // post_trans

__device__ __forceinline__ void inv3(const float* a, float* o) {
    float c00 = a[4] * a[8] - a[5] * a[7];
    float c01 = a[5] * a[6] - a[3] * a[8];
    float c02 = a[3] * a[7] - a[4] * a[6];
    float det = a[0] * c00 + a[1] * c01 + a[2] * c02;
    float id = 1.0f / det;
    o[0] = c00 * id;
    o[1] = (a[2] * a[7] - a[1] * a[8]) * id;
    o[2] = (a[1] * a[5] - a[2] * a[4]) * id;
    o[3] = c01 * id;
    o[4] = (a[0] * a[8] - a[2] * a[6]) * id;
    o[5] = (a[2] * a[3] - a[0] * a[5]) * id;
    o[6] = c02 * id;
    o[7] = (a[1] * a[6] - a[0] * a[7]) * id;
    o[8] = (a[0] * a[4] - a[1] * a[3]) * id;
}

// Fused: zero the output AND (block 0) compute per-camera transforms.
__global__ __launch_bounds__(256) void init_kernel(float4* __restrict__ out4,
                                                   int n4,
                                                   const float* __restrict__ c2l_r,
                                                   const float* __restrict__ c2l_t,
                                                   const float* __restrict__ intr,
                                                   const float* __restrict__ post_r,
                                                   const float* __restrict__ post_t,
                                                   const float* __restrict__ extra_r,
                                                   const float* __restrict__ extra_t) {
    int idx = (int)(blockIdx.x * 256u + threadIdx.x);
    if (idx < n4) out4[idx] = make_float4(0.f, 0.f, 0.f, 0.f);

    if (blockIdx.x == 0 && threadIdx.x < NCAM) {
        int n = threadIdx.x;
        float iK[9];
        inv3(intr + n * 9, iK);

        const float* R = c2l_r + n * 9;
        float comb[9];
#pragma unroll
        for (int i = 0; i < 3; i++)
#pragma unroll
            for (int j = 0; j < 3; j++)
                comb[i * 3 + j] = R[i * 3 + 0] * iK[0 * 3 + j] +
                                  R[i * 3 + 1] * iK[1 * 3 + j] +
                                  R[i * 3 + 2] * iK[2 * 3 + j];

        const float* E = extra_r;
#pragma unroll
        for (int i = 0; i < 3; i++)
#pragma unroll
            for (int j = 0; j < 3; j++)
                g_M[n * 9 + i * 3 + j] = E[i * 3 + 0] * comb[0 * 3 + j] +
                                         E[i * 3 + 1] * comb[1 * 3 + j] +
                                         E[i * 3 + 2] * comb[2 * 3 + j];

        const float* t = c2l_t + n * 3;
#pragma unroll
        for (int i = 0; i < 3; i++)
            g_T[n * 3 + i] = E[i * 3 + 0] * t[0] + E[i * 3 + 1] * t[1] +
                             E[i * 3 + 2] * t[2] + extra_t[i];

        float iPR[9];
        inv3(post_r + n * 9, iPR);
#pragma unroll
        for (int i = 0; i < 9; i++) g_iPR[n * 9 + i] = iPR[i];
#pragma unroll
        for (int i = 0; i < 3; i++) g_pT[n * 3 + i] = post_t[n * 3 + i];
    }
}

// One warp per (n, d, w) group; lane l owns image row h = l.
// Fast path (dominant): all valid h's map to ONE BEV cell -> branch-free
// batched loads (8 float4 in flight) + single flush. Generic fallback handles
// arbitrary per-h voxels via run-tracking.
__global__ __launch_bounds__(256) void scatter_kernel(const float* __restrict__ x,
                                                      float* __restrict__ out) {
    int grp = (int)((blockIdx.x * (unsigned)blockDim.x + threadIdx.x) >> 5);
    int lane = threadIdx.x & 31;
    if (grp >= NGRP) return;

    int w = grp % FW_;
    int nd = grp / FW_;      // n*DDIM + d
    int d = nd % DDIM;
    int n = nd / DDIM;

    float u = (float)w * (703.0f / 87.0f);
    float v = (float)lane * (255.0f / 31.0f);
    float dep = 1.0f + 0.5f * (float)d;

    const float* iPR = g_iPR + n * 9;
    const float* pT = g_pT + n * 3;
    const float* M = g_M + n * 9;
    const float* T = g_T + n * 3;

    float ax = u - pT[0], ay = v - pT[1], az = dep - pT[2];
    float px = iPR[0] * ax + iPR[1] * ay + iPR[2] * az;
    float py = iPR[3] * ax + iPR[4] * ay + iPR[5] * az;
    float pz = iPR[6] * ax + iPR[7] * ay + iPR[8] * az;

    float rx = px * pz, ry = py * pz, rz = pz;

    float gx = M[0] * rx + M[1] * ry + M[2] * rz + T[0];
    float gy = M[3] * rx + M[4] * ry + M[5] * rz + T[1];
    float gz = M[6] * rx + M[7] * ry + M[8] * rz + T[2];

    // voxelize: int32 cast truncates toward zero (matches jnp astype(int32))
    int cx = (int)((gx + 54.0f) * (1.0f / 0.3f));
    int cy = (int)((gy + 54.0f) * (1.0f / 0.3f));
    int cz = (int)((gz + 10.0f) * (1.0f / 20.0f));

    bool valid = (cx >= 0) & (cx < NXV) & (cy >= 0) & (cy < NYV) &
                 (cz >= 0) & (cz < NZV);
    int voxel = valid ? (cx * NYV + cy) : -1;

    unsigned vball = __ballot_sync(0xffffffffu, valid);
    if (vball == 0u) return;

    const float* base = x + (size_t)nd * (FH_ * HSTRIDE) + (size_t)w * CC;
    bool active = lane < (CC / 4);  // lanes 0..19 carry 4 channels each

    int vref = __shfl_sync(0xffffffffu, voxel, __ffs(vball) - 1);
    bool uni = __all_sync(0xffffffffu, !valid || (voxel == vref));

    if (uni) {
        // ---- fast path: single destination cell, validity via bit tests ----
        float4 acc = make_float4(0.f, 0.f, 0.f, 0.f);
#pragma unroll
        for (int h0 = 0; h0 < FH_; h0 += 8) {
            float4 f[8];
#pragma unroll
            for (int j = 0; j < 8; j++) {
                bool use = active && ((vball >> (h0 + j)) & 1u);
                f[j] = use ? __ldg((const float4*)(base + (size_t)(h0 + j) * HSTRIDE) + lane)
                           : make_float4(0.f, 0.f, 0.f, 0.f);
            }
#pragma unroll
            for (int j = 0; j < 8; j++) {
                acc.x += f[j].x; acc.y += f[j].y; acc.z += f[j].z; acc.w += f[j].w;
            }
        }
        if (active) {
#pragma unroll
            for (int i = 0; i < 4; i++)
                atomicAdd(out + (size_t)(lane * 4 + i) * NPOS + vref,
                          ((const float*)&acc)[i]);
        }
        return;
    }

    // ---- generic fallback: run-tracking over h ----
    float4 acc = make_float4(0.f, 0.f, 0.f, 0.f);
    int cur = -1;
#pragma unroll
    for (int hh = 0; hh < FH_; hh++) {
        int vx = __shfl_sync(0xffffffffu, voxel, hh);
        if (vx < 0) continue;
        if (vx != cur) {
            if (cur >= 0 && active) {
#pragma unroll
                for (int i = 0; i < 4; i++)
                    atomicAdd(out + (size_t)(lane * 4 + i) * NPOS + cur,
                              ((const float*)&acc)[i]);
            }
            cur = vx;
            acc = make_float4(0.f, 0.f, 0.f, 0.f);
        }
        if (active) {
            float4 f = __ldg((const float4*)(base + (size_t)hh * HSTRIDE) + lane);
            acc.x += f.x; acc.y += f.y; acc.z += f.z; acc.w += f.w;
        }
    }
    if (cur >= 0 && active) {
#pragma unroll
        for (int i = 0; i < 4; i++)
            atomicAdd(out + (size_t)(lane * 4 + i) * NPOS + cur,
                      ((const float*)&acc)[i]);
    }
}

extern "C" void kernel_launch(void* const* d_in, const int* in_sizes, int n_in,
                              void* d_out, int out_size) {
    const float* x       = (const float*)d_in[0];
    const float* c2l_r   = (const float*)d_in[1];
    const float* c2l_t   = (const float*)d_in[2];
    const float* intr    = (const float*)d_in[3];
    const float* post_r  = (const float*)d_in[4];
    const float* post_t  = (const float*)d_in[5];
    const float* extra_r = (const float*)d_in[6];
    const float* extra_t = (const float*)d_in[7];
    float* out = (float*)d_out;

    int n4 = out_size / 4;  // 2,592,000 float4
    int zblocks = (n4 + 255) / 256;
    init_kernel<<<zblocks, 256>>>((float4*)out, n4, c2l_r, c2l_t, intr,
                                  post_r, post_t, extra_r, extra_t);

    scatter_kernel<<<NGRP / 8, 256>>>(x, out);  // 7788 blocks, 8 warps each
}